// round 15
// baseline (speedup 1.0000x reference)
#include <cuda_runtime.h>
#include <cuda_bf16.h>
#include <math.h>
#include <stdint.h>

#define NXY   384
#define NROWS 768
#define DATA  4096
#define DM    128
#define EPS   1e-5f
#define KSPL  16
#define TGK   128

// ---------------- device scratch ----------------
__device__ __align__(16) __nv_bfloat16 g_Bh[DM * DATA];  // bf16 hi of gamma*W, [m][k]
__device__ __align__(16) __nv_bfloat16 g_Bl[DM * DATA];  // bf16 lo residual
__device__ float g_C1[DM], g_C2[DM];
__device__ float g_ssum[NROWS * 32];       // row-stat partials [row][ks*2+st]
__device__ float g_ssq[NROWS * 32];
__device__ float g_part[NROWS * KSPL * DM]; // GEMM partials [row][ks][m]
__device__ float g_exy[NROWS * DM];
__device__ __align__(16) __nv_bfloat16 g_Eh[NROWS * DM], g_El[NROWS * DM];   // exy bf16 split
__device__ __align__(16) __nv_bfloat16 g_Sh[NROWS * DM], g_Sl[NROWS * DM];   // self-weighted
__device__ __align__(16) __nv_bfloat16 g_Ch[NXY * DM],  g_Cl[NXY * DM];      // ex * wxy
__device__ float g_Mx[NXY * NXY], g_Gx[NXY * NXY];
__device__ float g_My[NXY * NXY], g_Gy[NXY * NXY];
__device__ float g_Gwt[NXY * NXY];         // [n][j]
__device__ float g_Gt[NXY * NXY];          // [n][j]
__device__ float g_Apart[NXY * NXY];       // [n][j]
__device__ float g_colsum[NXY];
__device__ float g_Araw[NXY];
__device__ float g_arowX[NXY], g_arowY[NXY];
__device__ float g_mpart[96 * DM];
__device__ unsigned g_mxbits[3];

// ---------------- helpers ----------------
__device__ __forceinline__ unsigned fOrd(float f) {
    unsigned u = __float_as_uint(f);
    return (u & 0x80000000u) ? ~u : (u | 0x80000000u);
}
__device__ __forceinline__ float fUnord(unsigned u) {
    return __uint_as_float((u & 0x80000000u) ? (u & 0x7FFFFFFFu) : ~u);
}
__device__ __forceinline__ uint32_t smem_u32(const void* p) {
    uint32_t a;
    asm("{ .reg .u64 t; cvta.to.shared.u64 t, %1; cvt.u32.u64 %0, t; }" : "=r"(a) : "l"(p));
    return a;
}
// fast bf16 hi/lo split of a pair using packed cvt: h = {hi:cvt(b), lo:cvt(a)}
__device__ __forceinline__ void cv2(float a, float b, uint32_t& h, uint32_t& l) {
    uint32_t hp;
    asm("cvt.rn.bf16x2.f32 %0, %1, %2;" : "=r"(hp) : "f"(b), "f"(a));
    float ah = __uint_as_float(hp << 16);
    float bh = __uint_as_float(hp & 0xffff0000u);
    float ra = a - ah, rb = b - bh;
    asm("cvt.rn.bf16x2.f32 %0, %1, %2;" : "=r"(l) : "f"(rb), "f"(ra));
    h = hp;
}
__device__ __forceinline__ void cv1(float a, __nv_bfloat16& h, __nv_bfloat16& l) {
    h = __float2bfloat16(a);
    l = __float2bfloat16(a - __bfloat162float(h));
}
__device__ __forceinline__ void ldsm4(uint32_t& r0, uint32_t& r1, uint32_t& r2,
                                      uint32_t& r3, uint32_t addr) {
    asm volatile("ldmatrix.sync.aligned.m8n8.x4.shared.b16 {%0,%1,%2,%3}, [%4];"
                 : "=r"(r0), "=r"(r1), "=r"(r2), "=r"(r3) : "r"(addr));
}
__device__ __forceinline__ void mma16816(float* c, uint32_t a0, uint32_t a1,
                                         uint32_t a2, uint32_t a3,
                                         uint32_t b0, uint32_t b1) {
    asm volatile(
        "mma.sync.aligned.m16n8k16.row.col.f32.bf16.bf16.f32 "
        "{%0,%1,%2,%3}, {%4,%5,%6,%7}, {%8,%9}, {%0,%1,%2,%3};"
        : "+f"(c[0]), "+f"(c[1]), "+f"(c[2]), "+f"(c[3])
        : "r"(a0), "r"(a1), "r"(a2), "r"(a3), "r"(b0), "r"(b1));
}

// ---------------- prep: Bh/Bl = bf16 split of gamma*W; C1/C2; init atomics ---
__global__ void __launch_bounds__(256) k_prepB(const float* __restrict__ W,
                                               const float* __restrict__ gamma,
                                               const float* __restrict__ beta) {
    int m = blockIdx.x, t = threadIdx.x;
    if (m == 0 && t == 0) {
        g_mxbits[0] = fOrd(-3.4e38f);
        g_mxbits[1] = fOrd(0.0f);       // cross-stage UB clamp (masked score = 0)
        g_mxbits[2] = fOrd(-3.4e38f);
    }
    float c1 = 0.f, c2 = 0.f;
#pragma unroll
    for (int i = 0; i < 4; i++) {
        int k4 = (t + i * 256) * 4;
        float4 w  = *(const float4*)(W + (size_t)m * DATA + k4);
        float4 gm = *(const float4*)(gamma + k4);
        float4 bt = *(const float4*)(beta + k4);
        c1 += gm.x * w.x + gm.y * w.y + gm.z * w.z + gm.w * w.w;
        c2 += bt.x * w.x + bt.y * w.y + bt.z * w.z + bt.w * w.w;
        float a0 = gm.x * w.x, a1 = gm.y * w.y, a2 = gm.z * w.z, a3 = gm.w * w.w;
        uint2 h, l;
        cv2(a0, a1, h.x, l.x); cv2(a2, a3, h.y, l.y);
        *(uint2*)((__nv_bfloat16*)g_Bh + (size_t)m * DATA + k4) = h;
        *(uint2*)((__nv_bfloat16*)g_Bl + (size_t)m * DATA + k4) = l;
    }
    __shared__ float r1[256], r2[256];
    r1[t] = c1; r2[t] = c2; __syncthreads();
    for (int off = 128; off; off >>= 1) {
        if (t < off) { r1[t] += r1[t + off]; r2[t] += r2[t + off]; }
        __syncthreads();
    }
    if (t == 0) { g_C1[m] = r1[0]; g_C2[m] = r2[0]; }
}

// ---------------- tensor-core GEMM: 64x128 tile, split-K=16, 2 K-chunks ------
// grid (12,1,16) = 192 blocks, 256 threads, ~102KB smem -> 2 blocks/SM, 1 wave.
__global__ void __launch_bounds__(256) k_gemm(const float* __restrict__ x,
                                              const float* __restrict__ y) {
    extern __shared__ __align__(16) char dsm[];
    const uint32_t LDB = 272;
    const uint32_t SM_AH = 0, SM_AL = 17408, SM_BH = 34816, SM_BL = 69632;
    uint32_t sb = smem_u32(dsm);
    int t = threadIdx.x, lane = t & 31, w = t >> 5;
    int wr = w & 3, wc = w >> 2;
    int r0 = blockIdx.x * 64, ks = blockIdx.z;
    const float* Ab = (r0 < NXY) ? x + (size_t)r0 * DATA
                                 : y + (size_t)(r0 - NXY) * DATA;

    float acc[4][2][4];
#pragma unroll
    for (int nb = 0; nb < 4; nb++)
#pragma unroll
        for (int s = 0; s < 2; s++)
#pragma unroll
            for (int q = 0; q < 4; q++) acc[nb][s][q] = 0.f;

    uint32_t aAddr = sb + SM_AH + (uint32_t)(wr * 16 + (lane & 15)) * LDB + ((lane >> 4) << 4);
    uint32_t bRow = (uint32_t)((lane & 7) + ((lane >> 4) << 3));
    uint32_t bAddr = sb + SM_BH + (uint32_t)(wc * 64 + bRow) * LDB + (((lane >> 3) & 1) << 4);

    for (int st = 0; st < 2; st++) {
        int kb = (ks * 2 + st) * TGK;
        if (st) __syncthreads();
        // B tiles: 128 m rows (bf16, pre-split)
#pragma unroll
        for (int i = 0; i < 8; i++) {
            int idx = t + i * 256;
            int m = idx >> 4, kq = (idx & 15) << 3;
            uint4 h = *(const uint4*)((const __nv_bfloat16*)g_Bh + (size_t)m * DATA + kb + kq);
            uint4 l = *(const uint4*)((const __nv_bfloat16*)g_Bl + (size_t)m * DATA + kb + kq);
            *(uint4*)(dsm + SM_BH + m * LDB + kq * 2) = h;
            *(uint4*)(dsm + SM_BL + m * LDB + kq * 2) = l;
        }
        // A tile: 64 rows, fp32 -> bf16 hi/lo + fused row stats
        {
            int kc = (t & 15) << 3;
#pragma unroll
            for (int i = 0; i < 4; i++) {
                int row = (t >> 4) + i * 16;
                const float* src = Ab + (size_t)row * DATA + kb + kc;
                float4 v0 = *(const float4*)src;
                float4 v1 = *(const float4*)(src + 4);
                float ls = v0.x + v0.y + v0.z + v0.w + v1.x + v1.y + v1.z + v1.w;
                float lq = v0.x*v0.x + v0.y*v0.y + v0.z*v0.z + v0.w*v0.w
                         + v1.x*v1.x + v1.y*v1.y + v1.z*v1.z + v1.w*v1.w;
#pragma unroll
                for (int o = 8; o; o >>= 1) {
                    ls += __shfl_xor_sync(0xffffffffu, ls, o);
                    lq += __shfl_xor_sync(0xffffffffu, lq, o);
                }
                if ((lane & 15) == 0) {
                    g_ssum[(size_t)(r0 + row) * 32 + ks * 2 + st] = ls;
                    g_ssq[(size_t)(r0 + row) * 32 + ks * 2 + st] = lq;
                }
                uint4 hi, lo;
                cv2(v0.x, v0.y, hi.x, lo.x); cv2(v0.z, v0.w, hi.y, lo.y);
                cv2(v1.x, v1.y, hi.z, lo.z); cv2(v1.z, v1.w, hi.w, lo.w);
                *(uint4*)(dsm + SM_AH + row * LDB + kc * 2) = hi;
                *(uint4*)(dsm + SM_AL + row * LDB + kc * 2) = lo;
            }
        }
        __syncthreads();
#pragma unroll
        for (int k8 = 0; k8 < 8; k8++) {
            uint32_t kOff = k8 * 32;
            uint32_t ah0, ah1, ah2, ah3, al0, al1, al2, al3;
            ldsm4(ah0, ah1, ah2, ah3, aAddr + kOff);
            ldsm4(al0, al1, al2, al3, aAddr + kOff + (SM_AL - SM_AH));
#pragma unroll
            for (int nb = 0; nb < 4; nb++) {
                uint32_t ba = bAddr + (uint32_t)(nb * 16) * LDB + kOff;
                uint32_t bh0, bh1, bh2, bh3, bl0, bl1, bl2, bl3;
                ldsm4(bh0, bh1, bh2, bh3, ba);
                ldsm4(bl0, bl1, bl2, bl3, ba + (SM_BL - SM_BH));
                mma16816(acc[nb][0], ah0, ah1, ah2, ah3, bh0, bh1);
                mma16816(acc[nb][0], ah0, ah1, ah2, ah3, bl0, bl1);
                mma16816(acc[nb][0], al0, al1, al2, al3, bh0, bh1);
                mma16816(acc[nb][1], ah0, ah1, ah2, ah3, bh2, bh3);
                mma16816(acc[nb][1], ah0, ah1, ah2, ah3, bl2, bl3);
                mma16816(acc[nb][1], al0, al1, al2, al3, bh2, bh3);
            }
        }
    }
    {
        int rA = r0 + wr * 16 + (lane >> 2);
        float* base = g_part + (size_t)rA * (KSPL * DM) + ks * DM;
        float* base8 = base + (size_t)8 * (KSPL * DM);
        int c0 = (lane & 3) * 2;
#pragma unroll
        for (int nb = 0; nb < 4; nb++)
#pragma unroll
            for (int s = 0; s < 2; s++) {
                int col = wc * 64 + nb * 16 + s * 8 + c0;
                *(float2*)(base + col)  = make_float2(acc[nb][s][0], acc[nb][s][1]);
                *(float2*)(base8 + col) = make_float2(acc[nb][s][2], acc[nb][s][3]);
            }
    }
}

// ---------------- epilogue: reduce + LN affine + nan0 + bf16 splits ----------
__global__ void __launch_bounds__(128) k_epi(const float* __restrict__ redb,
                                             const float* __restrict__ wx,
                                             const float* __restrict__ wy,
                                             const float* __restrict__ wxy) {
    __shared__ float s_mu, s_sq;
    int r = blockIdx.x, t = threadIdx.x;
    if (t < 32) {
        float v = g_ssum[(size_t)r * 32 + t];
#pragma unroll
        for (int o = 16; o; o >>= 1) v += __shfl_xor_sync(0xffffffffu, v, o);
        if (t == 0) s_mu = v * (1.f / DATA);
    } else if (t < 64) {
        float v = g_ssq[(size_t)r * 32 + (t - 32)];
#pragma unroll
        for (int o = 16; o; o >>= 1) v += __shfl_xor_sync(0xffffffffu, v, o);
        if (t == 32) s_sq = v;
    }
    __syncthreads();
    float mu = s_mu;
    float rstd = rsqrtf(s_sq * (1.f / DATA) - mu * mu + EPS);
    const float* p = g_part + (size_t)r * (KSPL * DM) + t;
    float acc = 0.f;
#pragma unroll
    for (int k = 0; k < KSPL; k++) acc += p[k * DM];
    float v = rstd * (acc - mu * g_C1[t]) + g_C2[t] + redb[t];
    if (isnan(v)) v = 0.f;
    size_t idx = (size_t)r * DM + t;
    g_exy[idx] = v;
    __nv_bfloat16 h, l;
    cv1(v, h, l);
    g_Eh[idx] = h; g_El[idx] = l;
    float ws = (r < NXY) ? wx[t] : wy[t];
    cv1(v * ws, h, l);
    g_Sh[idx] = h; g_Sl[idx] = l;
    if (r < NXY) {
        cv1(v * wxy[t], h, l);
        g_Ch[idx] = h; g_Cl[idx] = l;
    }
}

// ---------------- Gram via mma.sync: 64x32 tiles, bf16 pre-split -------------
// grid (12 nt, 6 jt, 3 z) = 216 blocks, 256 threads, ~85KB smem.
__global__ void __launch_bounds__(256) k_gram() {
    extern __shared__ __align__(16) char dsm[];
    const uint32_t LDB = 272;
    const uint32_t SM_AH = 0, SM_AL = 17408, SM_WH = 34816, SM_WL = 52224,
                   SM_BH = 69632, SM_BL = 78336;
    const uint32_t STRIDE_ST = 33;  // float stride of G stage (64x32 tile)
    uint32_t sb = smem_u32(dsm);
    int t = threadIdx.x, lane = t & 31, w = t >> 5;
    int role = w >> 2, wr = w & 3;   // role 0 = G, role 1 = M
    int nt = blockIdx.x, jt = blockIdx.y, z = blockIdx.z;
    size_t aOff = (z == 1) ? (size_t)NXY * DM : 0;   // A rows (jt side)
    size_t bOff = (z == 0) ? 0 : (size_t)NXY * DM;   // B rows (nt side)
    const __nv_bfloat16* AMh = (z == 2) ? g_Ch : g_Sh + aOff;
    const __nv_bfloat16* AMl = (z == 2) ? g_Cl : g_Sl + aOff;
    float* Mo = (z == 0) ? g_Mx : (z == 1) ? g_My : g_Gwt;
    float* Go = (z == 0) ? g_Gx : (z == 1) ? g_Gy : g_Gt;

    // prologue: pure bf16 copies (A plain, A weighted, B plain)
    {
        int kq = (t & 15) << 3;
#pragma unroll
        for (int i = 0; i < 4; i++) {
            int row = (t >> 4) + i * 16;
            size_t ra = aOff + (size_t)(jt * 64 + row) * DM + kq;
            *(uint4*)(dsm + SM_AH + row * LDB + kq * 2) = *(const uint4*)(g_Eh + ra);
            *(uint4*)(dsm + SM_AL + row * LDB + kq * 2) = *(const uint4*)(g_El + ra);
            size_t rm = (size_t)(jt * 64 + row) * DM + kq;
            *(uint4*)(dsm + SM_WH + row * LDB + kq * 2) = *(const uint4*)(AMh + rm);
            *(uint4*)(dsm + SM_WL + row * LDB + kq * 2) = *(const uint4*)(AMl + rm);
            if (i < 2) {
                size_t rb = bOff + (size_t)(nt * 32 + row) * DM + kq;
                *(uint4*)(dsm + SM_BH + row * LDB + kq * 2) = *(const uint4*)(g_Eh + rb);
                *(uint4*)(dsm + SM_BL + row * LDB + kq * 2) = *(const uint4*)(g_El + rb);
            }
        }
    }
    __syncthreads();

    float acc[2][2][4];
#pragma unroll
    for (int nb = 0; nb < 2; nb++)
#pragma unroll
        for (int s = 0; s < 2; s++)
#pragma unroll
            for (int q = 0; q < 4; q++) acc[nb][s][q] = 0.f;

    uint32_t opBase = role ? SM_WH : SM_AH;
    uint32_t aAddr = sb + opBase + (uint32_t)(wr * 16 + (lane & 15)) * LDB + ((lane >> 4) << 4);
    uint32_t bRow = (uint32_t)((lane & 7) + ((lane >> 4) << 3));
    uint32_t bAddr = sb + SM_BH + bRow * LDB + (((lane >> 3) & 1) << 4);

#pragma unroll
    for (int k8 = 0; k8 < 8; k8++) {
        uint32_t kOff = k8 * 32;
        uint32_t ah0, ah1, ah2, ah3, al0, al1, al2, al3;
        ldsm4(ah0, ah1, ah2, ah3, aAddr + kOff);
        ldsm4(al0, al1, al2, al3, aAddr + kOff + 17408);
#pragma unroll
        for (int nb = 0; nb < 2; nb++) {
            uint32_t ba = bAddr + (uint32_t)(nb * 16) * LDB + kOff;
            uint32_t bh0, bh1, bh2, bh3, bl0, bl1, bl2, bl3;
            ldsm4(bh0, bh1, bh2, bh3, ba);
            ldsm4(bl0, bl1, bl2, bl3, ba + 8704);
            mma16816(acc[nb][0], ah0, ah1, ah2, ah3, bh0, bh1);
            mma16816(acc[nb][0], ah0, ah1, ah2, ah3, bl0, bl1);
            mma16816(acc[nb][0], al0, al1, al2, al3, bh0, bh1);
            mma16816(acc[nb][1], ah0, ah1, ah2, ah3, bh2, bh3);
            mma16816(acc[nb][1], ah0, ah1, ah2, ah3, bl2, bl3);
            mma16816(acc[nb][1], al0, al1, al2, al3, bh2, bh3);
        }
    }
    __syncthreads();   // all ldsm done before stage-area overwrite

    int r0l = wr * 16 + (lane >> 2);
    int c0l = (lane & 3) * 2;
    float* stage = (float*)dsm;

    if (role == 0) {
#pragma unroll
        for (int nb = 0; nb < 2; nb++)
#pragma unroll
            for (int s = 0; s < 2; s++) {
                int lc = nb * 16 + s * 8 + c0l;
                int col = nt * 32 + lc;
                int row0 = jt * 64 + r0l, row1 = row0 + 8;
                float g0 = acc[nb][s][0], g1 = acc[nb][s][1];
                float g2 = acc[nb][s][2], g3 = acc[nb][s][3];
                if (z < 2) {
                    *(float2*)(Go + (size_t)row0 * NXY + col) = make_float2(g0, g1);
                    *(float2*)(Go + (size_t)row1 * NXY + col) = make_float2(g2, g3);
                    stage[r0l * STRIDE_ST + lc]           = g0;
                    stage[r0l * STRIDE_ST + lc + 1]       = g1;
                    stage[(r0l + 8) * STRIDE_ST + lc]     = g2;
                    stage[(r0l + 8) * STRIDE_ST + lc + 1] = g3;
                } else {
                    Go[(size_t)col * NXY + row0]       = g0;
                    Go[(size_t)(col + 1) * NXY + row0] = g1;
                    Go[(size_t)col * NXY + row1]       = g2;
                    Go[(size_t)(col + 1) * NXY + row1] = g3;
                }
            }
    }
    __syncthreads();
    __shared__ float wmax[4];
    if (role == 1) {
        float mxv = -3.4e38f;
#pragma unroll
        for (int nb = 0; nb < 2; nb++)
#pragma unroll
            for (int s = 0; s < 2; s++) {
                int lc = nb * 16 + s * 8 + c0l;
                int col = nt * 32 + lc;
                int row0 = jt * 64 + r0l, row1 = row0 + 8;
                float m0 = acc[nb][s][0], m1 = acc[nb][s][1];
                float m2 = acc[nb][s][2], m3 = acc[nb][s][3];
                if (z < 2) {
                    *(float2*)(Mo + (size_t)row0 * NXY + col) = make_float2(m0, m1);
                    *(float2*)(Mo + (size_t)row1 * NXY + col) = make_float2(m2, m3);
                    float g0 = stage[r0l * STRIDE_ST + lc];
                    float g1 = stage[r0l * STRIDE_ST + lc + 1];
                    float g2 = stage[(r0l + 8) * STRIDE_ST + lc];
                    float g3 = stage[(r0l + 8) * STRIDE_ST + lc + 1];
                    float s0 = (g0 < 0.f) ? 0.f : m0; if (row0 == col)     s0 = -3.4e38f;
                    float s1 = (g1 < 0.f) ? 0.f : m1; if (row0 == col + 1) s1 = -3.4e38f;
                    float s2 = (g2 < 0.f) ? 0.f : m2; if (row1 == col)     s2 = -3.4e38f;
                    float s3 = (g3 < 0.f) ? 0.f : m3; if (row1 == col + 1) s3 = -3.4e38f;
                    mxv = fmaxf(mxv, fmaxf(fmaxf(s0, s1), fmaxf(s2, s3)));
                } else {
                    Mo[(size_t)col * NXY + row0]       = m0;
                    Mo[(size_t)(col + 1) * NXY + row0] = m1;
                    Mo[(size_t)col * NXY + row1]       = m2;
                    Mo[(size_t)(col + 1) * NXY + row1] = m3;
                    // UB: 2*top1 >= top1+top2 >= any pair score; cancels in softmax
                    mxv = fmaxf(mxv, 2.f * fmaxf(fmaxf(m0, m1), fmaxf(m2, m3)));
                }
            }
#pragma unroll
        for (int o = 16; o; o >>= 1)
            mxv = fmaxf(mxv, __shfl_xor_sync(0xffffffffu, mxv, o));
        if (lane == 0) wmax[wr] = mxv;
    }
    __syncthreads();
    if (t == 128) {
        float mx = fmaxf(fmaxf(wmax[0], wmax[1]), fmaxf(wmax[2], wmax[3]));
        int slot = (z == 0) ? 0 : (z == 1) ? 2 : 1;
        atomicMax(&g_mxbits[slot], fOrd(mx));
    }
}

// ---------------- fused score reductions ----------------
__global__ void __launch_bounds__(384) k_scores() {
    __shared__ float red[NXY];
    int b = blockIdx.x, t = threadIdx.x;
    if (b < 2 * NXY) {
        int isY = (b >= NXY);
        int j = isY ? b - NXY : b;
        const float* M = isY ? g_My : g_Mx;
        const float* G = isY ? g_Gy : g_Gx;
        float mx = fUnord(g_mxbits[isY ? 2 : 0]);
        float e = 0.f;
        if (t != j) {
            float sc = (G[(size_t)j * NXY + t] < 0.f) ? 0.f : M[(size_t)j * NXY + t];
            e = __expf(sc - mx);
        }
        red[t] = e; __syncthreads();
        if (t < 128) red[t] += red[t + 128] + red[t + 256];
        __syncthreads();
        for (int off = 64; off; off >>= 1) {
            if (t < off) red[t] += red[t + off];
            __syncthreads();
        }
        if (t == 0) (isY ? g_arowY : g_arowX)[j] = red[0];
    } else {
        __shared__ __align__(16) float gc[NXY], ec[NXY];
        int n = b - 2 * NXY;
        float mx2 = fUnord(g_mxbits[1]);
        float c0 = __expf(-mx2);
        gc[t] = g_Gt[(size_t)n * NXY + t];
        ec[t] = __expf(g_Gwt[(size_t)n * NXY + t] - 0.5f * mx2);
        __syncthreads();
        float gj = gc[t], ej = ec[t], thr = -gj;
        float ejc = fmaxf(ej, 1e-30f);
        float rr = c0 / ejc;
        float acc = 0.f;
        const float4* gc4 = (const float4*)gc;
        const float4* ec4 = (const float4*)ec;
#pragma unroll 2
        for (int k4 = 0; k4 < NXY / 4; k4++) {
            float4 g4 = gc4[k4], e4 = ec4[k4];
            acc += (g4.x < thr) ? rr : e4.x;
            acc += (g4.y < thr) ? rr : e4.y;
            acc += (g4.z < thr) ? rr : e4.z;
            acc += (g4.w < thr) ? rr : e4.w;
        }
        acc -= (gj < thr) ? rr : ej;   // remove k == j
        float perj = ejc * acc;
        g_Apart[(size_t)n * NXY + t] = perj;
        red[t] = perj; __syncthreads();
        if (t < 128) red[t] += red[t + 128] + red[t + 256];
        __syncthreads();
        for (int off = 64; off; off >>= 1) {
            if (t < off) red[t] += red[t + off];
            __syncthreads();
        }
        if (t == 0) g_colsum[n] = red[0];
    }
}

// ---------------- Araw column sums + mean partials (merged) ----------------
__global__ void __launch_bounds__(128) k_red() {
    int b = blockIdx.x, t = threadIdx.x;
    if (b < 12) {
        __shared__ float sred[4][32];
        int j = b * 32 + (t & 31), grp = t >> 5;
        float s = 0.f;
        int n0 = grp * 96;
#pragma unroll 8
        for (int n = n0; n < n0 + 96; n++) s += g_Apart[(size_t)n * NXY + j];
        sred[grp][t & 31] = s;
        __syncthreads();
        if (t < 32) g_Araw[b * 32 + t] = sred[0][t] + sred[1][t] + sred[2][t] + sred[3][t];
    } else {
        int bb = b - 12;
        float s = 0.f;
#pragma unroll
        for (int rr = 0; rr < 8; rr++) s += g_exy[(size_t)(bb * 8 + rr) * DM + t];
        g_mpart[(size_t)bb * DM + t] = s;
    }
}

// ---------------- fused tail: 3 mix stages + FFNs + QNet head ----------------
__global__ void __launch_bounds__(512) k_tail(const float* __restrict__ fW,
                                              const float* __restrict__ fb,
                                              const float* __restrict__ qW1,
                                              const float* __restrict__ qb1,
                                              const float* __restrict__ qW2,
                                              const float* __restrict__ qb2,
                                              float* __restrict__ out) {
    extern __shared__ __align__(16) float dynf[];
    float* fWs = dynf;                 // [d][m] transposed, stride 129
    float* qWs = dynf + 128 * 129;
    __shared__ float csh[NROWS], part[4][DM], part2[4][DM], rsh[DM], zsh[DM];
    __shared__ float wred[16];
    __shared__ float s_scale, s_sA, s_sB;
    int t = threadIdx.x, m = t & 127, g = t >> 7;
    int wid = t >> 5, lane = t & 31;

    for (int i = t; i < DM * DM; i += 512) {
        int r = i >> 7, c = i & 127;
        fWs[c * 129 + r] = fW[i];
        qWs[c * 129 + r] = qW1[i];
    }

    // ======== stage 1: x-x pairs + global mean + ffn ========
    {
        float av = (t < NXY) ? g_arowX[t] : 0.f;
        if (t < NXY) csh[t] = av;
#pragma unroll
        for (int o = 16; o; o >>= 1) av += __shfl_xor_sync(0xffffffffu, av, o);
        if (lane == 0) wred[wid] = av;
        __syncthreads();
        if (t == 0) {
            float s = 0.f;
#pragma unroll
            for (int i = 0; i < 16; i++) s += wred[i];
            s_scale = 2.f / s;
        }
        float p = 0.f;
        int j0 = g * 96;
#pragma unroll 8
        for (int j = j0; j < j0 + 96; j++)
            p = fmaf(csh[j], g_exy[(size_t)j * DM + m], p);
        part[g][m] = p;
        float p2 = 0.f;
        int b0 = g * 24;
#pragma unroll 8
        for (int bb = b0; bb < b0 + 24; bb++)
            p2 += g_mpart[(size_t)bb * DM + m];
        part2[g][m] = p2;
        __syncthreads();
        if (g == 0)
            rsh[m] = (part[0][m] + part[1][m] + part[2][m] + part[3][m]) * s_scale
                   + (part2[0][m] + part2[1][m] + part2[2][m] + part2[3][m]) * (1.f / NROWS);
        __syncthreads();
        float a = 0.f;
        int d0 = g * 32;
#pragma unroll 8
        for (int d = d0; d < d0 + 32; d++)
            a = fmaf(fWs[d * 129 + m], rsh[d], a);
        part[g][m] = a;
        __syncthreads();
        if (g == 0)
            zsh[m] = part[0][m] + part[1][m] + part[2][m] + part[3][m] + fb[m] + rsh[m];
        __syncthreads();
    }

    // ======== stage 2: cross pairs + ffn ========
    {
        float cv = (t < NXY) ? g_colsum[t] : 0.f;
        float cr = cv;
#pragma unroll
        for (int o = 16; o; o >>= 1) cr += __shfl_xor_sync(0xffffffffu, cr, o);
        if (lane == 0) wred[wid] = cr;
        __syncthreads();
        if (t == 0) {
            float s = 0.f;
#pragma unroll
            for (int i = 0; i < 16; i++) s += wred[i];
            s_sA = 2.f / s; s_sB = 1.f / s;
        }
        __syncthreads();
        if (t < NXY) {
            csh[t] = g_Araw[t] * s_sA;
            csh[NXY + t] = cv * s_sB;
        }
        __syncthreads();
        float p = 0.f;
        int j0 = g * 192;
#pragma unroll 8
        for (int j = j0; j < j0 + 192; j++)
            p = fmaf(csh[j], g_exy[(size_t)j * DM + m], p);
        part[g][m] = p;
        __syncthreads();
        if (g == 0)
            rsh[m] = part[0][m] + part[1][m] + part[2][m] + part[3][m] + zsh[m];
        __syncthreads();
        float a = 0.f;
        int d0 = g * 32;
#pragma unroll 8
        for (int d = d0; d < d0 + 32; d++)
            a = fmaf(fWs[d * 129 + m], rsh[d], a);
        part[g][m] = a;
        __syncthreads();
        if (g == 0)
            zsh[m] = part[0][m] + part[1][m] + part[2][m] + part[3][m] + fb[m] + rsh[m];
        __syncthreads();
    }

    // ======== stage 3: y-y pairs + ffn ========
    {
        float av = (t < NXY) ? g_arowY[t] : 0.f;
        if (t < NXY) csh[t] = av;
#pragma unroll
        for (int o = 16; o; o >>= 1) av += __shfl_xor_sync(0xffffffffu, av, o);
        if (lane == 0) wred[wid] = av;
        __syncthreads();
        if (t == 0) {
            float s = 0.f;
#pragma unroll
            for (int i = 0; i < 16; i++) s += wred[i];
            s_scale = 2.f / s;
        }
        float p = 0.f;
        int j0 = g * 96;
#pragma unroll 8
        for (int j = j0; j < j0 + 96; j++)
            p = fmaf(csh[j], g_exy[(size_t)(NXY + j) * DM + m], p);
        part[g][m] = p;
        __syncthreads();
        if (g == 0)
            rsh[m] = (part[0][m] + part[1][m] + part[2][m] + part[3][m]) * s_scale + zsh[m];
        __syncthreads();
        float a = 0.f;
        int d0 = g * 32;
#pragma unroll 8
        for (int d = d0; d < d0 + 32; d++)
            a = fmaf(fWs[d * 129 + m], rsh[d], a);
        part[g][m] = a;
        __syncthreads();
        if (g == 0) {
            float z = part[0][m] + part[1][m] + part[2][m] + part[3][m] + fb[m] + rsh[m];
            if (isnan(z)) z = 0.f;
            zsh[m] = z;
            out[2 + m] = z;
        }
        __syncthreads();
    }

    // ======== head: QNet ========
    {
        float a = 0.f;
        int d0 = g * 32;
#pragma unroll 8
        for (int d = d0; d < d0 + 32; d++)
            a = fmaf(qWs[d * 129 + m], zsh[d], a);
        part[g][m] = a;
        __syncthreads();
        if (g == 0)
            rsh[m] = fmaxf(part[0][m] + part[1][m] + part[2][m] + part[3][m] + qb1[m], 0.f);
        __syncthreads();
        if (t < 64) {
            int o = t >> 5, ln = t & 31;
            float s = 0.f;
#pragma unroll
            for (int d = ln; d < DM; d += 32)
                s = fmaf(qW2[(size_t)o * DM + d], rsh[d], s);
#pragma unroll
            for (int off = 16; off; off >>= 1) s += __shfl_xor_sync(0xffffffffu, s, off);
            if (ln == 0) {
                float v = s + qb2[o];
                if (isnan(v)) v = 0.f;
                out[o] = v;
            }
        }
    }
}

// ---------------- launch ----------------
extern "C" void kernel_launch(void* const* d_in, const int* in_sizes, int n_in,
                              void* d_out, int out_size) {
    const float* input_x = (const float*)d_in[0];
    const float* input_y = (const float*)d_in[1];
    const float* ln_gamma = (const float*)d_in[2];
    const float* ln_beta = (const float*)d_in[3];
    const float* red_W = (const float*)d_in[4];
    const float* red_b = (const float*)d_in[5];
    const float* weight_x = (const float*)d_in[6];
    const float* weight_y = (const float*)d_in[7];
    const float* weight_xy = (const float*)d_in[8];
    const float* ffn_W = (const float*)d_in[9];
    const float* ffn_b = (const float*)d_in[10];
    const float* q_W1 = (const float*)d_in[11];
    const float* q_b1 = (const float*)d_in[12];
    const float* q_W2 = (const float*)d_in[13];
    const float* q_b2 = (const float*)d_in[14];
    float* out = (float*)d_out;
    (void)n_in; (void)in_sizes; (void)out_size;

    cudaFuncSetAttribute(k_gemm, cudaFuncAttributeMaxDynamicSharedMemorySize, 104448);
    cudaFuncSetAttribute(k_gram, cudaFuncAttributeMaxDynamicSharedMemorySize, 87040);
    cudaFuncSetAttribute(k_tail, cudaFuncAttributeMaxDynamicSharedMemorySize, 132096);

    k_prepB<<<DM, 256>>>(red_W, ln_gamma, ln_beta);
    k_gemm<<<dim3(NROWS / 64, 1, KSPL), 256, 104448>>>(input_x, input_y);
    k_epi<<<NROWS, 128>>>(red_b, weight_x, weight_y, weight_xy);
    k_gram<<<dim3(12, 6, 3), 256, 87040>>>();
    k_scores<<<3 * NXY, NXY>>>();
    k_red<<<108, 128>>>();
    k_tail<<<1, 512, 132096>>>(ffn_W, ffn_b, q_W1, q_b1, q_W2, q_b2, out);
}

// round 16
// speedup vs baseline: 1.1155x; 1.1155x over previous
#include <cuda_runtime.h>
#include <cuda_bf16.h>
#include <math.h>
#include <stdint.h>

#define NXY   384
#define NROWS 768
#define DATA  4096
#define DM    128
#define EPS   1e-5f
#define KSPL  32
#define TGK   128

// ---------------- device scratch ----------------
__device__ __align__(16) __nv_bfloat16 g_Bh[DM * DATA];  // bf16 hi of gamma*W, [m][k]
__device__ __align__(16) __nv_bfloat16 g_Bl[DM * DATA];  // bf16 lo residual
__device__ float g_C1[DM], g_C2[DM];
__device__ float g_ssum[NROWS * KSPL];     // row-stat partials [row][ks]
__device__ float g_ssq[NROWS * KSPL];
__device__ float g_part[NROWS * KSPL * DM]; // GEMM partials [row][ks][m]
__device__ float g_exy[NROWS * DM];
__device__ __align__(16) __nv_bfloat16 g_Eh[NROWS * DM], g_El[NROWS * DM];   // exy bf16 split
__device__ __align__(16) __nv_bfloat16 g_Sh[NROWS * DM], g_Sl[NROWS * DM];   // self-weighted
__device__ __align__(16) __nv_bfloat16 g_Ch[NXY * DM],  g_Cl[NXY * DM];      // ex * wxy
__device__ float g_Mx[NXY * NXY], g_Gx[NXY * NXY];
__device__ float g_My[NXY * NXY], g_Gy[NXY * NXY];
__device__ float g_Gwt[NXY * NXY];         // [n][j]
__device__ float g_Gt[NXY * NXY];          // [n][j]
__device__ float g_Apart[NXY * NXY];       // [n][j]
__device__ float g_colsum[NXY];
__device__ float g_Araw[NXY];
__device__ float g_arowX[NXY], g_arowY[NXY];
__device__ float g_mpart[96 * DM];
__device__ unsigned g_mxbits[3];

// ---------------- helpers ----------------
__device__ __forceinline__ unsigned fOrd(float f) {
    unsigned u = __float_as_uint(f);
    return (u & 0x80000000u) ? ~u : (u | 0x80000000u);
}
__device__ __forceinline__ float fUnord(unsigned u) {
    return __uint_as_float((u & 0x80000000u) ? (u & 0x7FFFFFFFu) : ~u);
}
__device__ __forceinline__ uint32_t smem_u32(const void* p) {
    uint32_t a;
    asm("{ .reg .u64 t; cvta.to.shared.u64 t, %1; cvt.u32.u64 %0, t; }" : "=r"(a) : "l"(p));
    return a;
}
// fast bf16 hi/lo split of a pair using packed cvt
__device__ __forceinline__ void cv2(float a, float b, uint32_t& h, uint32_t& l) {
    uint32_t hp;
    asm("cvt.rn.bf16x2.f32 %0, %1, %2;" : "=r"(hp) : "f"(b), "f"(a));
    float ah = __uint_as_float(hp << 16);
    float bh = __uint_as_float(hp & 0xffff0000u);
    float ra = a - ah, rb = b - bh;
    asm("cvt.rn.bf16x2.f32 %0, %1, %2;" : "=r"(l) : "f"(rb), "f"(ra));
    h = hp;
}
__device__ __forceinline__ void cv1(float a, __nv_bfloat16& h, __nv_bfloat16& l) {
    h = __float2bfloat16(a);
    l = __float2bfloat16(a - __bfloat162float(h));
}
__device__ __forceinline__ void ldsm4(uint32_t& r0, uint32_t& r1, uint32_t& r2,
                                      uint32_t& r3, uint32_t addr) {
    asm volatile("ldmatrix.sync.aligned.m8n8.x4.shared.b16 {%0,%1,%2,%3}, [%4];"
                 : "=r"(r0), "=r"(r1), "=r"(r2), "=r"(r3) : "r"(addr));
}
__device__ __forceinline__ void mma16816(float* c, uint32_t a0, uint32_t a1,
                                         uint32_t a2, uint32_t a3,
                                         uint32_t b0, uint32_t b1) {
    asm volatile(
        "mma.sync.aligned.m16n8k16.row.col.f32.bf16.bf16.f32 "
        "{%0,%1,%2,%3}, {%4,%5,%6,%7}, {%8,%9}, {%0,%1,%2,%3};"
        : "+f"(c[0]), "+f"(c[1]), "+f"(c[2]), "+f"(c[3])
        : "r"(a0), "r"(a1), "r"(a2), "r"(a3), "r"(b0), "r"(b1));
}

// ---------------- prep: Bh/Bl = bf16 split of gamma*W; C1/C2; init atomics ---
__global__ void __launch_bounds__(256) k_prepB(const float* __restrict__ W,
                                               const float* __restrict__ gamma,
                                               const float* __restrict__ beta) {
    int m = blockIdx.x, t = threadIdx.x;
    if (m == 0 && t == 0) {
        g_mxbits[0] = fOrd(-3.4e38f);
        g_mxbits[1] = fOrd(0.0f);       // cross-stage UB clamp (masked score = 0)
        g_mxbits[2] = fOrd(-3.4e38f);
    }
    float c1 = 0.f, c2 = 0.f;
#pragma unroll
    for (int i = 0; i < 4; i++) {
        int k4 = (t + i * 256) * 4;
        float4 w  = *(const float4*)(W + (size_t)m * DATA + k4);
        float4 gm = *(const float4*)(gamma + k4);
        float4 bt = *(const float4*)(beta + k4);
        c1 += gm.x * w.x + gm.y * w.y + gm.z * w.z + gm.w * w.w;
        c2 += bt.x * w.x + bt.y * w.y + bt.z * w.z + bt.w * w.w;
        float a0 = gm.x * w.x, a1 = gm.y * w.y, a2 = gm.z * w.z, a3 = gm.w * w.w;
        uint2 h, l;
        cv2(a0, a1, h.x, l.x); cv2(a2, a3, h.y, l.y);
        *(uint2*)((__nv_bfloat16*)g_Bh + (size_t)m * DATA + k4) = h;
        *(uint2*)((__nv_bfloat16*)g_Bl + (size_t)m * DATA + k4) = l;
    }
    __shared__ float r1[256], r2[256];
    r1[t] = c1; r2[t] = c2; __syncthreads();
    for (int off = 128; off; off >>= 1) {
        if (t < off) { r1[t] += r1[t + off]; r2[t] += r2[t + off]; }
        __syncthreads();
    }
    if (t == 0) { g_C1[m] = r1[0]; g_C2[m] = r2[0]; }
}

// ---------------- tensor-core GEMM: 64x128 tile, split-K=32 -------------------
// grid (12,1,32) = 384 blocks, 256 threads, ~102KB smem -> 2 blocks/SM.
__global__ void __launch_bounds__(256) k_gemm(const float* __restrict__ x,
                                              const float* __restrict__ y) {
    extern __shared__ __align__(16) char dsm[];
    const uint32_t LDB = 272;
    const uint32_t SM_AH = 0, SM_AL = 17408, SM_BH = 34816, SM_BL = 69632;
    uint32_t sb = smem_u32(dsm);
    int t = threadIdx.x, lane = t & 31, w = t >> 5;
    int wr = w & 3, wc = w >> 2;
    int r0 = blockIdx.x * 64, ks = blockIdx.z, kb = ks * TGK;
    const float* Ab = (r0 < NXY) ? x + (size_t)r0 * DATA
                                 : y + (size_t)(r0 - NXY) * DATA;

    // B tiles: 128 m rows (bf16, pre-split)
#pragma unroll
    for (int i = 0; i < 8; i++) {
        int idx = t + i * 256;
        int m = idx >> 4, kq = (idx & 15) << 3;
        uint4 h = *(const uint4*)((const __nv_bfloat16*)g_Bh + (size_t)m * DATA + kb + kq);
        uint4 l = *(const uint4*)((const __nv_bfloat16*)g_Bl + (size_t)m * DATA + kb + kq);
        *(uint4*)(dsm + SM_BH + m * LDB + kq * 2) = h;
        *(uint4*)(dsm + SM_BL + m * LDB + kq * 2) = l;
    }
    // A tile: 64 rows, fp32 -> bf16 hi/lo + fused row stats
    {
        int kc = (t & 15) << 3;
#pragma unroll
        for (int i = 0; i < 4; i++) {
            int row = (t >> 4) + i * 16;
            const float* src = Ab + (size_t)row * DATA + kb + kc;
            float4 v0 = *(const float4*)src;
            float4 v1 = *(const float4*)(src + 4);
            float ls = v0.x + v0.y + v0.z + v0.w + v1.x + v1.y + v1.z + v1.w;
            float lq = v0.x*v0.x + v0.y*v0.y + v0.z*v0.z + v0.w*v0.w
                     + v1.x*v1.x + v1.y*v1.y + v1.z*v1.z + v1.w*v1.w;
#pragma unroll
            for (int o = 8; o; o >>= 1) {
                ls += __shfl_xor_sync(0xffffffffu, ls, o);
                lq += __shfl_xor_sync(0xffffffffu, lq, o);
            }
            if ((lane & 15) == 0) {
                g_ssum[(size_t)(r0 + row) * KSPL + ks] = ls;
                g_ssq[(size_t)(r0 + row) * KSPL + ks] = lq;
            }
            uint4 hi, lo;
            cv2(v0.x, v0.y, hi.x, lo.x); cv2(v0.z, v0.w, hi.y, lo.y);
            cv2(v1.x, v1.y, hi.z, lo.z); cv2(v1.z, v1.w, hi.w, lo.w);
            *(uint4*)(dsm + SM_AH + row * LDB + kc * 2) = hi;
            *(uint4*)(dsm + SM_AL + row * LDB + kc * 2) = lo;
        }
    }
    __syncthreads();

    float acc[4][2][4];
#pragma unroll
    for (int nb = 0; nb < 4; nb++)
#pragma unroll
        for (int s = 0; s < 2; s++)
#pragma unroll
            for (int q = 0; q < 4; q++) acc[nb][s][q] = 0.f;

    uint32_t aAddr = sb + SM_AH + (uint32_t)(wr * 16 + (lane & 15)) * LDB + ((lane >> 4) << 4);
    uint32_t bRow = (uint32_t)((lane & 7) + ((lane >> 4) << 3));
    uint32_t bAddr = sb + SM_BH + (uint32_t)(wc * 64 + bRow) * LDB + (((lane >> 3) & 1) << 4);

#pragma unroll
    for (int k8 = 0; k8 < 8; k8++) {
        uint32_t kOff = k8 * 32;
        uint32_t ah0, ah1, ah2, ah3, al0, al1, al2, al3;
        ldsm4(ah0, ah1, ah2, ah3, aAddr + kOff);
        ldsm4(al0, al1, al2, al3, aAddr + kOff + (SM_AL - SM_AH));
#pragma unroll
        for (int nb = 0; nb < 4; nb++) {
            uint32_t ba = bAddr + (uint32_t)(nb * 16) * LDB + kOff;
            uint32_t bh0, bh1, bh2, bh3, bl0, bl1, bl2, bl3;
            ldsm4(bh0, bh1, bh2, bh3, ba);
            ldsm4(bl0, bl1, bl2, bl3, ba + (SM_BL - SM_BH));
            mma16816(acc[nb][0], ah0, ah1, ah2, ah3, bh0, bh1);
            mma16816(acc[nb][0], ah0, ah1, ah2, ah3, bl0, bl1);
            mma16816(acc[nb][0], al0, al1, al2, al3, bh0, bh1);
            mma16816(acc[nb][1], ah0, ah1, ah2, ah3, bh2, bh3);
            mma16816(acc[nb][1], ah0, ah1, ah2, ah3, bl2, bl3);
            mma16816(acc[nb][1], al0, al1, al2, al3, bh2, bh3);
        }
    }
    {
        int rA = r0 + wr * 16 + (lane >> 2);
        float* base = g_part + (size_t)rA * (KSPL * DM) + ks * DM;
        float* base8 = base + (size_t)8 * (KSPL * DM);
        int c0 = (lane & 3) * 2;
#pragma unroll
        for (int nb = 0; nb < 4; nb++)
#pragma unroll
            for (int s = 0; s < 2; s++) {
                int col = wc * 64 + nb * 16 + s * 8 + c0;
                *(float2*)(base + col)  = make_float2(acc[nb][s][0], acc[nb][s][1]);
                *(float2*)(base8 + col) = make_float2(acc[nb][s][2], acc[nb][s][3]);
            }
    }
}

// ---------------- epilogue: reduce + LN affine + nan0 + bf16 splits ----------
__global__ void __launch_bounds__(128) k_epi(const float* __restrict__ redb,
                                             const float* __restrict__ wx,
                                             const float* __restrict__ wy,
                                             const float* __restrict__ wxy) {
    __shared__ float s_mu, s_sq;
    int r = blockIdx.x, t = threadIdx.x;
    if (t < 32) {
        float v = g_ssum[(size_t)r * KSPL + t];
#pragma unroll
        for (int o = 16; o; o >>= 1) v += __shfl_xor_sync(0xffffffffu, v, o);
        if (t == 0) s_mu = v * (1.f / DATA);
    } else if (t < 64) {
        float v = g_ssq[(size_t)r * KSPL + (t - 32)];
#pragma unroll
        for (int o = 16; o; o >>= 1) v += __shfl_xor_sync(0xffffffffu, v, o);
        if (t == 32) s_sq = v;
    }
    __syncthreads();
    float mu = s_mu;
    float rstd = rsqrtf(s_sq * (1.f / DATA) - mu * mu + EPS);
    const float* p = g_part + (size_t)r * (KSPL * DM) + t;
    float acc = 0.f;
#pragma unroll
    for (int k = 0; k < KSPL; k++) acc += p[k * DM];
    float v = rstd * (acc - mu * g_C1[t]) + g_C2[t] + redb[t];
    if (isnan(v)) v = 0.f;
    size_t idx = (size_t)r * DM + t;
    g_exy[idx] = v;
    __nv_bfloat16 h, l;
    cv1(v, h, l);
    g_Eh[idx] = h; g_El[idx] = l;
    float ws = (r < NXY) ? wx[t] : wy[t];
    cv1(v * ws, h, l);
    g_Sh[idx] = h; g_Sl[idx] = l;
    if (r < NXY) {
        cv1(v * wxy[t], h, l);
        g_Ch[idx] = h; g_Cl[idx] = l;
    }
}

// ---------------- Gram via mma.sync: 64x32 tiles, bf16 pre-split -------------
// grid (12 nt, 6 jt, 3 z) = 216 blocks, 256 threads, ~85KB smem.
__global__ void __launch_bounds__(256) k_gram() {
    extern __shared__ __align__(16) char dsm[];
    const uint32_t LDB = 272;
    const uint32_t SM_AH = 0, SM_AL = 17408, SM_WH = 34816, SM_WL = 52224,
                   SM_BH = 69632, SM_BL = 78336;
    const uint32_t STRIDE_ST = 33;  // float stride of G stage (64x32 tile)
    uint32_t sb = smem_u32(dsm);
    int t = threadIdx.x, lane = t & 31, w = t >> 5;
    int role = w >> 2, wr = w & 3;   // role 0 = G, role 1 = M
    int nt = blockIdx.x, jt = blockIdx.y, z = blockIdx.z;
    size_t aOff = (z == 1) ? (size_t)NXY * DM : 0;   // A rows (jt side)
    size_t bOff = (z == 0) ? 0 : (size_t)NXY * DM;   // B rows (nt side)
    const __nv_bfloat16* AMh = (z == 2) ? g_Ch : g_Sh + aOff;
    const __nv_bfloat16* AMl = (z == 2) ? g_Cl : g_Sl + aOff;
    float* Mo = (z == 0) ? g_Mx : (z == 1) ? g_My : g_Gwt;
    float* Go = (z == 0) ? g_Gx : (z == 1) ? g_Gy : g_Gt;

    // prologue: pure bf16 copies (A plain, A weighted, B plain)
    {
        int kq = (t & 15) << 3;
#pragma unroll
        for (int i = 0; i < 4; i++) {
            int row = (t >> 4) + i * 16;
            size_t ra = aOff + (size_t)(jt * 64 + row) * DM + kq;
            *(uint4*)(dsm + SM_AH + row * LDB + kq * 2) = *(const uint4*)(g_Eh + ra);
            *(uint4*)(dsm + SM_AL + row * LDB + kq * 2) = *(const uint4*)(g_El + ra);
            size_t rm = (size_t)(jt * 64 + row) * DM + kq;
            *(uint4*)(dsm + SM_WH + row * LDB + kq * 2) = *(const uint4*)(AMh + rm);
            *(uint4*)(dsm + SM_WL + row * LDB + kq * 2) = *(const uint4*)(AMl + rm);
            if (i < 2) {
                size_t rb = bOff + (size_t)(nt * 32 + row) * DM + kq;
                *(uint4*)(dsm + SM_BH + row * LDB + kq * 2) = *(const uint4*)(g_Eh + rb);
                *(uint4*)(dsm + SM_BL + row * LDB + kq * 2) = *(const uint4*)(g_El + rb);
            }
        }
    }
    __syncthreads();

    float acc[2][2][4];
#pragma unroll
    for (int nb = 0; nb < 2; nb++)
#pragma unroll
        for (int s = 0; s < 2; s++)
#pragma unroll
            for (int q = 0; q < 4; q++) acc[nb][s][q] = 0.f;

    uint32_t opBase = role ? SM_WH : SM_AH;
    uint32_t aAddr = sb + opBase + (uint32_t)(wr * 16 + (lane & 15)) * LDB + ((lane >> 4) << 4);
    uint32_t bRow = (uint32_t)((lane & 7) + ((lane >> 4) << 3));
    uint32_t bAddr = sb + SM_BH + bRow * LDB + (((lane >> 3) & 1) << 4);

#pragma unroll
    for (int k8 = 0; k8 < 8; k8++) {
        uint32_t kOff = k8 * 32;
        uint32_t ah0, ah1, ah2, ah3, al0, al1, al2, al3;
        ldsm4(ah0, ah1, ah2, ah3, aAddr + kOff);
        ldsm4(al0, al1, al2, al3, aAddr + kOff + 17408);
#pragma unroll
        for (int nb = 0; nb < 2; nb++) {
            uint32_t ba = bAddr + (uint32_t)(nb * 16) * LDB + kOff;
            uint32_t bh0, bh1, bh2, bh3, bl0, bl1, bl2, bl3;
            ldsm4(bh0, bh1, bh2, bh3, ba);
            ldsm4(bl0, bl1, bl2, bl3, ba + 8704);
            mma16816(acc[nb][0], ah0, ah1, ah2, ah3, bh0, bh1);
            mma16816(acc[nb][0], ah0, ah1, ah2, ah3, bl0, bl1);
            mma16816(acc[nb][0], al0, al1, al2, al3, bh0, bh1);
            mma16816(acc[nb][1], ah0, ah1, ah2, ah3, bh2, bh3);
            mma16816(acc[nb][1], ah0, ah1, ah2, ah3, bl2, bl3);
            mma16816(acc[nb][1], al0, al1, al2, al3, bh2, bh3);
        }
    }
    __syncthreads();   // all ldsm done before stage-area overwrite

    int r0l = wr * 16 + (lane >> 2);
    int c0l = (lane & 3) * 2;
    float* stage = (float*)dsm;

    if (role == 0) {
#pragma unroll
        for (int nb = 0; nb < 2; nb++)
#pragma unroll
            for (int s = 0; s < 2; s++) {
                int lc = nb * 16 + s * 8 + c0l;
                int col = nt * 32 + lc;
                int row0 = jt * 64 + r0l, row1 = row0 + 8;
                float g0 = acc[nb][s][0], g1 = acc[nb][s][1];
                float g2 = acc[nb][s][2], g3 = acc[nb][s][3];
                if (z < 2) {
                    *(float2*)(Go + (size_t)row0 * NXY + col) = make_float2(g0, g1);
                    *(float2*)(Go + (size_t)row1 * NXY + col) = make_float2(g2, g3);
                    stage[r0l * STRIDE_ST + lc]           = g0;
                    stage[r0l * STRIDE_ST + lc + 1]       = g1;
                    stage[(r0l + 8) * STRIDE_ST + lc]     = g2;
                    stage[(r0l + 8) * STRIDE_ST + lc + 1] = g3;
                } else {
                    Go[(size_t)col * NXY + row0]       = g0;
                    Go[(size_t)(col + 1) * NXY + row0] = g1;
                    Go[(size_t)col * NXY + row1]       = g2;
                    Go[(size_t)(col + 1) * NXY + row1] = g3;
                }
            }
    }
    __syncthreads();
    __shared__ float wmax[4];
    if (role == 1) {
        float mxv = -3.4e38f;
#pragma unroll
        for (int nb = 0; nb < 2; nb++)
#pragma unroll
            for (int s = 0; s < 2; s++) {
                int lc = nb * 16 + s * 8 + c0l;
                int col = nt * 32 + lc;
                int row0 = jt * 64 + r0l, row1 = row0 + 8;
                float m0 = acc[nb][s][0], m1 = acc[nb][s][1];
                float m2 = acc[nb][s][2], m3 = acc[nb][s][3];
                if (z < 2) {
                    *(float2*)(Mo + (size_t)row0 * NXY + col) = make_float2(m0, m1);
                    *(float2*)(Mo + (size_t)row1 * NXY + col) = make_float2(m2, m3);
                    float g0 = stage[r0l * STRIDE_ST + lc];
                    float g1 = stage[r0l * STRIDE_ST + lc + 1];
                    float g2 = stage[(r0l + 8) * STRIDE_ST + lc];
                    float g3 = stage[(r0l + 8) * STRIDE_ST + lc + 1];
                    float s0 = (g0 < 0.f) ? 0.f : m0; if (row0 == col)     s0 = -3.4e38f;
                    float s1 = (g1 < 0.f) ? 0.f : m1; if (row0 == col + 1) s1 = -3.4e38f;
                    float s2 = (g2 < 0.f) ? 0.f : m2; if (row1 == col)     s2 = -3.4e38f;
                    float s3 = (g3 < 0.f) ? 0.f : m3; if (row1 == col + 1) s3 = -3.4e38f;
                    mxv = fmaxf(mxv, fmaxf(fmaxf(s0, s1), fmaxf(s2, s3)));
                } else {
                    Mo[(size_t)col * NXY + row0]       = m0;
                    Mo[(size_t)(col + 1) * NXY + row0] = m1;
                    Mo[(size_t)col * NXY + row1]       = m2;
                    Mo[(size_t)(col + 1) * NXY + row1] = m3;
                    // UB: 2*top1 >= top1+top2 >= any pair score; cancels in softmax
                    mxv = fmaxf(mxv, 2.f * fmaxf(fmaxf(m0, m1), fmaxf(m2, m3)));
                }
            }
#pragma unroll
        for (int o = 16; o; o >>= 1)
            mxv = fmaxf(mxv, __shfl_xor_sync(0xffffffffu, mxv, o));
        if (lane == 0) wmax[wr] = mxv;
    }
    __syncthreads();
    if (t == 128) {
        float mx = fmaxf(fmaxf(wmax[0], wmax[1]), fmaxf(wmax[2], wmax[3]));
        int slot = (z == 0) ? 0 : (z == 1) ? 2 : 1;
        atomicMax(&g_mxbits[slot], fOrd(mx));
    }
}

// ---------------- fused score reductions ----------------
// grid 64 + 384: [0,64) self rows (warp-per-row, 12 warps), [64,448) cross cols
__global__ void __launch_bounds__(384) k_scores() {
    int b = blockIdx.x, t = threadIdx.x;
    if (b < 64) {
        // warp-per-row self exp-sums: row j = b*12 + warp; j<384 -> X, else Y
        int w = t >> 5, lane = t & 31;
        int jg = b * 12 + w;
        int isY = (jg >= NXY);
        int j = isY ? jg - NXY : jg;
        const float* M = isY ? g_My : g_Mx;
        const float* G = isY ? g_Gy : g_Gx;
        float mx = fUnord(g_mxbits[isY ? 2 : 0]);
        float e = 0.f;
#pragma unroll
        for (int i = 0; i < 12; i++) {
            int k = lane + i * 32;
            float sc = (G[(size_t)j * NXY + k] < 0.f) ? 0.f : M[(size_t)j * NXY + k];
            float ev = __expf(sc - mx);
            e += (k == j) ? 0.f : ev;
        }
#pragma unroll
        for (int o = 16; o; o >>= 1) e += __shfl_xor_sync(0xffffffffu, e, o);
        if (lane == 0) (isY ? g_arowY : g_arowX)[j] = e;
    } else {
        __shared__ __align__(16) float gc[NXY], ec[NXY], red[NXY];
        int n = b - 64;
        float mx2 = fUnord(g_mxbits[1]);
        float c0 = __expf(-mx2);
        gc[t] = g_Gt[(size_t)n * NXY + t];
        ec[t] = __expf(g_Gwt[(size_t)n * NXY + t] - 0.5f * mx2);
        __syncthreads();
        float gj = gc[t], ej = ec[t], thr = -gj;
        float ejc = fmaxf(ej, 1e-30f);
        float rr = c0 / ejc;
        // acc = sum_k (masked ? c0/ejc : ec[k]); perj = ejc*acc = ej*se + c0*cnt
        float acc = 0.f;
        const float4* gc4 = (const float4*)gc;
        const float4* ec4 = (const float4*)ec;
#pragma unroll 2
        for (int k4 = 0; k4 < NXY / 4; k4++) {
            float4 g4 = gc4[k4], e4 = ec4[k4];
            acc += (g4.x < thr) ? rr : e4.x;
            acc += (g4.y < thr) ? rr : e4.y;
            acc += (g4.z < thr) ? rr : e4.z;
            acc += (g4.w < thr) ? rr : e4.w;
        }
        acc -= (gj < thr) ? rr : ej;   // remove k == j
        float perj = ejc * acc;
        g_Apart[(size_t)n * NXY + t] = perj;
        red[t] = perj; __syncthreads();
        if (t < 128) red[t] += red[t + 128] + red[t + 256];
        __syncthreads();
        for (int off = 64; off; off >>= 1) {
            if (t < off) red[t] += red[t + off];
            __syncthreads();
        }
        if (t == 0) g_colsum[n] = red[0];
    }
}

// ---------------- Araw column sums + mean partials (merged) ----------------
__global__ void __launch_bounds__(128) k_red() {
    int b = blockIdx.x, t = threadIdx.x;
    if (b < 12) {
        __shared__ float sred[4][32];
        int j = b * 32 + (t & 31), grp = t >> 5;
        float s = 0.f;
        int n0 = grp * 96;
#pragma unroll 8
        for (int n = n0; n < n0 + 96; n++) s += g_Apart[(size_t)n * NXY + j];
        sred[grp][t & 31] = s;
        __syncthreads();
        if (t < 32) g_Araw[b * 32 + t] = sred[0][t] + sred[1][t] + sred[2][t] + sred[3][t];
    } else {
        int bb = b - 12;
        float s = 0.f;
#pragma unroll
        for (int rr = 0; rr < 8; rr++) s += g_exy[(size_t)(bb * 8 + rr) * DM + t];
        g_mpart[(size_t)bb * DM + t] = s;
    }
}

// ---------------- fused tail: 3 mix stages + FFNs + QNet head ----------------
__global__ void __launch_bounds__(512) k_tail(const float* __restrict__ fW,
                                              const float* __restrict__ fb,
                                              const float* __restrict__ qW1,
                                              const float* __restrict__ qb1,
                                              const float* __restrict__ qW2,
                                              const float* __restrict__ qb2,
                                              float* __restrict__ out) {
    extern __shared__ __align__(16) float dynf[];
    float* fWs = dynf;                 // [d][m] transposed, stride 129
    float* qWs = dynf + 128 * 129;
    __shared__ float csh[NROWS], part[4][DM], part2[4][DM], rsh[DM], zsh[DM];
    __shared__ float wred[16];
    __shared__ float s_scale, s_sA, s_sB;
    int t = threadIdx.x, m = t & 127, g = t >> 7;
    int wid = t >> 5, lane = t & 31;

    for (int i = t; i < DM * DM; i += 512) {
        int r = i >> 7, c = i & 127;
        fWs[c * 129 + r] = fW[i];
        qWs[c * 129 + r] = qW1[i];
    }

    // ======== stage 1: x-x pairs + global mean + ffn ========
    {
        float av = (t < NXY) ? g_arowX[t] : 0.f;
        if (t < NXY) csh[t] = av;
#pragma unroll
        for (int o = 16; o; o >>= 1) av += __shfl_xor_sync(0xffffffffu, av, o);
        if (lane == 0) wred[wid] = av;
        __syncthreads();
        if (t == 0) {
            float s = 0.f;
#pragma unroll
            for (int i = 0; i < 16; i++) s += wred[i];
            s_scale = 2.f / s;
        }
        float p = 0.f;
        int j0 = g * 96;
#pragma unroll 8
        for (int j = j0; j < j0 + 96; j++)
            p = fmaf(csh[j], g_exy[(size_t)j * DM + m], p);
        part[g][m] = p;
        float p2 = 0.f;
        int b0 = g * 24;
#pragma unroll 8
        for (int bb = b0; bb < b0 + 24; bb++)
            p2 += g_mpart[(size_t)bb * DM + m];
        part2[g][m] = p2;
        __syncthreads();
        if (g == 0)
            rsh[m] = (part[0][m] + part[1][m] + part[2][m] + part[3][m]) * s_scale
                   + (part2[0][m] + part2[1][m] + part2[2][m] + part2[3][m]) * (1.f / NROWS);
        __syncthreads();
        float a = 0.f;
        int d0 = g * 32;
#pragma unroll 8
        for (int d = d0; d < d0 + 32; d++)
            a = fmaf(fWs[d * 129 + m], rsh[d], a);
        part[g][m] = a;
        __syncthreads();
        if (g == 0)
            zsh[m] = part[0][m] + part[1][m] + part[2][m] + part[3][m] + fb[m] + rsh[m];
        __syncthreads();
    }

    // ======== stage 2: cross pairs + ffn ========
    {
        float cv = (t < NXY) ? g_colsum[t] : 0.f;
        float cr = cv;
#pragma unroll
        for (int o = 16; o; o >>= 1) cr += __shfl_xor_sync(0xffffffffu, cr, o);
        if (lane == 0) wred[wid] = cr;
        __syncthreads();
        if (t == 0) {
            float s = 0.f;
#pragma unroll
            for (int i = 0; i < 16; i++) s += wred[i];
            s_sA = 2.f / s; s_sB = 1.f / s;
        }
        __syncthreads();
        if (t < NXY) {
            csh[t] = g_Araw[t] * s_sA;
            csh[NXY + t] = cv * s_sB;
        }
        __syncthreads();
        float p = 0.f;
        int j0 = g * 192;
#pragma unroll 8
        for (int j = j0; j < j0 + 192; j++)
            p = fmaf(csh[j], g_exy[(size_t)j * DM + m], p);
        part[g][m] = p;
        __syncthreads();
        if (g == 0)
            rsh[m] = part[0][m] + part[1][m] + part[2][m] + part[3][m] + zsh[m];
        __syncthreads();
        float a = 0.f;
        int d0 = g * 32;
#pragma unroll 8
        for (int d = d0; d < d0 + 32; d++)
            a = fmaf(fWs[d * 129 + m], rsh[d], a);
        part[g][m] = a;
        __syncthreads();
        if (g == 0)
            zsh[m] = part[0][m] + part[1][m] + part[2][m] + part[3][m] + fb[m] + rsh[m];
        __syncthreads();
    }

    // ======== stage 3: y-y pairs + ffn ========
    {
        float av = (t < NXY) ? g_arowY[t] : 0.f;
        if (t < NXY) csh[t] = av;
#pragma unroll
        for (int o = 16; o; o >>= 1) av += __shfl_xor_sync(0xffffffffu, av, o);
        if (lane == 0) wred[wid] = av;
        __syncthreads();
        if (t == 0) {
            float s = 0.f;
#pragma unroll
            for (int i = 0; i < 16; i++) s += wred[i];
            s_scale = 2.f / s;
        }
        float p = 0.f;
        int j0 = g * 96;
#pragma unroll 8
        for (int j = j0; j < j0 + 96; j++)
            p = fmaf(csh[j], g_exy[(size_t)(NXY + j) * DM + m], p);
        part[g][m] = p;
        __syncthreads();
        if (g == 0)
            rsh[m] = (part[0][m] + part[1][m] + part[2][m] + part[3][m]) * s_scale + zsh[m];
        __syncthreads();
        float a = 0.f;
        int d0 = g * 32;
#pragma unroll 8
        for (int d = d0; d < d0 + 32; d++)
            a = fmaf(fWs[d * 129 + m], rsh[d], a);
        part[g][m] = a;
        __syncthreads();
        if (g == 0) {
            float z = part[0][m] + part[1][m] + part[2][m] + part[3][m] + fb[m] + rsh[m];
            if (isnan(z)) z = 0.f;
            zsh[m] = z;
            out[2 + m] = z;
        }
        __syncthreads();
    }

    // ======== head: QNet ========
    {
        float a = 0.f;
        int d0 = g * 32;
#pragma unroll 8
        for (int d = d0; d < d0 + 32; d++)
            a = fmaf(qWs[d * 129 + m], zsh[d], a);
        part[g][m] = a;
        __syncthreads();
        if (g == 0)
            rsh[m] = fmaxf(part[0][m] + part[1][m] + part[2][m] + part[3][m] + qb1[m], 0.f);
        __syncthreads();
        if (t < 64) {
            int o = t >> 5, ln = t & 31;
            float s = 0.f;
#pragma unroll
            for (int d = ln; d < DM; d += 32)
                s = fmaf(qW2[(size_t)o * DM + d], rsh[d], s);
#pragma unroll
            for (int off = 16; off; off >>= 1) s += __shfl_xor_sync(0xffffffffu, s, off);
            if (ln == 0) {
                float v = s + qb2[o];
                if (isnan(v)) v = 0.f;
                out[o] = v;
            }
        }
    }
}

// ---------------- launch ----------------
extern "C" void kernel_launch(void* const* d_in, const int* in_sizes, int n_in,
                              void* d_out, int out_size) {
    const float* input_x = (const float*)d_in[0];
    const float* input_y = (const float*)d_in[1];
    const float* ln_gamma = (const float*)d_in[2];
    const float* ln_beta = (const float*)d_in[3];
    const float* red_W = (const float*)d_in[4];
    const float* red_b = (const float*)d_in[5];
    const float* weight_x = (const float*)d_in[6];
    const float* weight_y = (const float*)d_in[7];
    const float* weight_xy = (const float*)d_in[8];
    const float* ffn_W = (const float*)d_in[9];
    const float* ffn_b = (const float*)d_in[10];
    const float* q_W1 = (const float*)d_in[11];
    const float* q_b1 = (const float*)d_in[12];
    const float* q_W2 = (const float*)d_in[13];
    const float* q_b2 = (const float*)d_in[14];
    float* out = (float*)d_out;
    (void)n_in; (void)in_sizes; (void)out_size;

    cudaFuncSetAttribute(k_gemm, cudaFuncAttributeMaxDynamicSharedMemorySize, 104448);
    cudaFuncSetAttribute(k_gram, cudaFuncAttributeMaxDynamicSharedMemorySize, 87040);
    cudaFuncSetAttribute(k_tail, cudaFuncAttributeMaxDynamicSharedMemorySize, 132096);

    k_prepB<<<DM, 256>>>(red_W, ln_gamma, ln_beta);
    k_gemm<<<dim3(NROWS / 64, 1, KSPL), 256, 104448>>>(input_x, input_y);
    k_epi<<<NROWS, 128>>>(red_b, weight_x, weight_y, weight_xy);
    k_gram<<<dim3(12, 6, 3), 256, 87040>>>();
    k_scores<<<448, NXY>>>();
    k_red<<<108, 128>>>();
    k_tail<<<1, 512, 132096>>>(ffn_W, ffn_b, q_W1, q_b1, q_W2, q_b2, out);
}